// round 4
// baseline (speedup 1.0000x reference)
#include <cuda_runtime.h>
#include <cstdint>

#define HW 3136

// Scratch (device globals: no runtime allocation allowed)
__device__ float g_mid1[16 * 128 * HW];
__device__ float g_sc1[128], g_bi1[128];
__device__ float g_sc2[128], g_bi2[128];
__device__ float g_sc3[512], g_bi3[512];

// ---------------------------------------------------------------------------
__global__ void bn_prep(const float* __restrict__ g1, const float* __restrict__ b1,
                        const float* __restrict__ m1, const float* __restrict__ v1,
                        const float* __restrict__ g2, const float* __restrict__ b2,
                        const float* __restrict__ m2, const float* __restrict__ v2,
                        const float* __restrict__ g3, const float* __restrict__ b3,
                        const float* __restrict__ m3, const float* __restrict__ v3) {
    int i = threadIdx.x;  // 512 threads
    if (i < 128) {
        float s = g1[i] * rsqrtf(v1[i] + 1e-5f);
        g_sc1[i] = s;
        g_bi1[i] = b1[i] - m1[i] * s;
        float s2 = g2[i] * rsqrtf(v2[i] + 1e-5f);
        g_sc2[i] = s2;
        g_bi2[i] = b2[i] - m2[i] * s2;
    }
    float s3 = g3[i] * rsqrtf(v3[i] + 1e-5f);
    g_sc3[i] = s3;
    g_bi3[i] = b3[i] - m3[i] * s3;
}

// Common decode: 224 threads = 7 warps; warp = patch column, lane: r=l>>2 row,
// cp=l&3 col-pair; thread owns 2 adjacent pixels. Mask is warp-uniform.

// ---------------------------------------------------------------------------
// K1: 1x1 conv (128 -> 16 oc per block) + BN1 + ReLU + mask premult
// grid = (b, g, pr, half)
// ---------------------------------------------------------------------------
__global__ __launch_bounds__(224, 4) void k1(const float* __restrict__ x,
                                             const float* __restrict__ mask,
                                             const float* __restrict__ w1) {
    __shared__ __align__(16) float ws[2048];  // [ic][16]

    const int t = threadIdx.x, blk = blockIdx.x;
    const int h = blk & 1;
    const int rest = blk >> 1;
    const int pr = rest % 7;
    const int bg = rest / 7;
    const int g = bg & 3, b = bg >> 2;

    for (int e = t; e < 2048; e += 224) {
        int j = e >> 7, ic = e & 127;
        ws[ic * 16 + j] = w1[(g * 32 + h * 16 + j) * 128 + ic];
    }
    __syncthreads();

    const int w = t >> 5, l = t & 31;
    const int r = l >> 2, cp = l & 3;
    const int grow = pr * 8 + r;
    const int col = w * 8 + cp * 2;
    const float m = mask[((b * 4 + g) * 7 + pr) * 7 + w];

    float* op = g_mid1 + (size_t)(b * 128 + g * 32 + h * 16) * HW + grow * 56 + col;

    if (m != 0.f) {
        const float* xp = x + (size_t)(b * 512 + g * 128) * HW + grow * 56 + col;
        float a0[16], a1[16];
#pragma unroll
        for (int j = 0; j < 16; j++) { a0[j] = 0.f; a1[j] = 0.f; }

        for (int ic0 = 0; ic0 < 128; ic0 += 8) {
            float2 xv[8];
#pragma unroll
            for (int u = 0; u < 8; u++)
                xv[u] = *(const float2*)(xp + (size_t)(ic0 + u) * HW);
#pragma unroll
            for (int u = 0; u < 8; u++) {
                const float4* wp = (const float4*)(ws + (ic0 + u) * 16);
#pragma unroll
                for (int j = 0; j < 4; j++) {
                    float4 q = wp[j];
                    a0[4 * j + 0] = fmaf(xv[u].x, q.x, a0[4 * j + 0]);
                    a0[4 * j + 1] = fmaf(xv[u].x, q.y, a0[4 * j + 1]);
                    a0[4 * j + 2] = fmaf(xv[u].x, q.z, a0[4 * j + 2]);
                    a0[4 * j + 3] = fmaf(xv[u].x, q.w, a0[4 * j + 3]);
                    a1[4 * j + 0] = fmaf(xv[u].y, q.x, a1[4 * j + 0]);
                    a1[4 * j + 1] = fmaf(xv[u].y, q.y, a1[4 * j + 1]);
                    a1[4 * j + 2] = fmaf(xv[u].y, q.z, a1[4 * j + 2]);
                    a1[4 * j + 3] = fmaf(xv[u].y, q.w, a1[4 * j + 3]);
                }
            }
        }
#pragma unroll
        for (int j = 0; j < 16; j++) {
            int c = h * 16 + j;
            float s = g_sc1[g * 32 + c], bb = g_bi1[g * 32 + c];
            float v0 = fmaxf(fmaf(m * a0[j], s, bb), 0.f) * m;
            float v1 = fmaxf(fmaf(m * a1[j], s, bb), 0.f) * m;
            *(float2*)(op + (size_t)j * HW) = make_float2(v0, v1);
        }
    } else {
        float2 z = make_float2(0.f, 0.f);
#pragma unroll
        for (int j = 0; j < 16; j++) *(float2*)(op + (size_t)j * HW) = z;
    }
}

// ---------------------------------------------------------------------------
// K23: fused 3x3 conv (32->32) + BN2 + ReLU + mask  THEN  1x1 conv (32->128)
//      + BN3 + residual + ReLU.  conv3 is 1x1 (no halo), so the conv2 result
//      for this thread's 2 pixels lives entirely in registers (p0/p1[32]).
// grid = (b, g, pr); 224 threads
// ---------------------------------------------------------------------------
__global__ __launch_bounds__(224, 2) void k23(const float* __restrict__ x,
                                              const float* __restrict__ mask,
                                              const float* __restrict__ w2,
                                              const float* __restrict__ w3,
                                              float* __restrict__ out) {
    extern __shared__ __align__(16) float sm[];
    float* ws2 = sm;          // 9216: [ic][dy][dx][32oc]
    float* ws3 = sm + 9216;   // 4096: [ic][128oc]

    const int t = threadIdx.x, blk = blockIdx.x;
    const int pr = blk % 7;
    const int bg = blk / 7;
    const int g = bg & 3, b = bg >> 2;

    for (int e = t; e < 9216; e += 224) {
        int oc = e / 288;
        int rem = e - oc * 288;
        int ic = rem / 9;
        int k = rem - ic * 9;
        ws2[(ic * 9 + k) * 32 + oc] = w2[g * 9216 + e];
    }
    for (int e = t; e < 4096; e += 224) {
        int oc = e >> 5, ic = e & 31;
        ws3[ic * 128 + oc] = w3[g * 4096 + e];
    }
    __syncthreads();

    const int w = t >> 5, l = t & 31;
    const int r = l >> 2, cp = l & 3;
    const int grow = pr * 8 + r;
    const int col = w * 8 + cp * 2;
    const float m = mask[((b * 4 + g) * 7 + pr) * 7 + w];

    const float* resp = x + (size_t)(b * 512 + g * 128) * HW + grow * 56 + col;
    float* op = out + (size_t)(b * 512 + g * 128) * HW + grow * 56 + col;

    if (m != 0.f) {
        // ---- conv2: 3x3, all 32 oc into registers ----
        const float* mb = g_mid1 + (size_t)(b * 128 + g * 32) * HW + col;
        float p0[32], p1[32];
#pragma unroll
        for (int j = 0; j < 32; j++) { p0[j] = 0.f; p1[j] = 0.f; }

#pragma unroll 1
        for (int ic = 0; ic < 32; ic++) {
            const float* pic = mb + (size_t)ic * HW;
            float xm[3], x2[3];
            float2 xc[3];
#pragma unroll
            for (int dy = 0; dy < 3; dy++) {
                int yy = grow - 1 + dy;
                bool v = (yy >= 0) && (yy < 56);
                const float* p = pic + yy * 56;
                xm[dy] = (v && col > 0) ? p[-1] : 0.f;
                xc[dy] = v ? *(const float2*)p : make_float2(0.f, 0.f);
                x2[dy] = (v && col < 54) ? p[2] : 0.f;
            }
#pragma unroll
            for (int dy = 0; dy < 3; dy++) {
                const float4* wp = (const float4*)(ws2 + (ic * 9 + dy * 3) * 32);
                float q0 = xm[dy], q1 = xc[dy].x, q2 = xc[dy].y, q3 = x2[dy];
#pragma unroll
                for (int j = 0; j < 8; j++) {
                    float4 wa = wp[j];
                    float4 wb = wp[8 + j];
                    float4 wc = wp[16 + j];
                    p0[4 * j + 0] = fmaf(q0, wa.x, fmaf(q1, wb.x, fmaf(q2, wc.x, p0[4 * j + 0])));
                    p0[4 * j + 1] = fmaf(q0, wa.y, fmaf(q1, wb.y, fmaf(q2, wc.y, p0[4 * j + 1])));
                    p0[4 * j + 2] = fmaf(q0, wa.z, fmaf(q1, wb.z, fmaf(q2, wc.z, p0[4 * j + 2])));
                    p0[4 * j + 3] = fmaf(q0, wa.w, fmaf(q1, wb.w, fmaf(q2, wc.w, p0[4 * j + 3])));
                    p1[4 * j + 0] = fmaf(q1, wa.x, fmaf(q2, wb.x, fmaf(q3, wc.x, p1[4 * j + 0])));
                    p1[4 * j + 1] = fmaf(q1, wa.y, fmaf(q2, wb.y, fmaf(q3, wc.y, p1[4 * j + 1])));
                    p1[4 * j + 2] = fmaf(q1, wa.z, fmaf(q2, wb.z, fmaf(q3, wc.z, p1[4 * j + 2])));
                    p1[4 * j + 3] = fmaf(q1, wa.w, fmaf(q2, wb.w, fmaf(q3, wc.w, p1[4 * j + 3])));
                }
            }
        }
        // bn2 + relu + mask (in place)
#pragma unroll
        for (int j = 0; j < 32; j++) {
            float s = g_sc2[g * 32 + j], bb = g_bi2[g * 32 + j];
            p0[j] = fmaxf(fmaf(p0[j], s, bb), 0.f) * m;
            p1[j] = fmaxf(fmaf(p1[j], s, bb), 0.f) * m;
        }

        // ---- conv3: 1x1, 32 -> 128 in chunks of 16 oc ----
#pragma unroll 1
        for (int q = 0; q < 8; q++) {
            float c0[16], c1[16];
#pragma unroll
            for (int j = 0; j < 16; j++) { c0[j] = 0.f; c1[j] = 0.f; }
#pragma unroll 2
            for (int ic = 0; ic < 32; ic++) {
                float pv0 = p0[ic], pv1 = p1[ic];
                const float4* wp = (const float4*)(ws3 + ic * 128 + q * 16);
#pragma unroll
                for (int j = 0; j < 4; j++) {
                    float4 qw = wp[j];
                    c0[4 * j + 0] = fmaf(pv0, qw.x, c0[4 * j + 0]);
                    c0[4 * j + 1] = fmaf(pv0, qw.y, c0[4 * j + 1]);
                    c0[4 * j + 2] = fmaf(pv0, qw.z, c0[4 * j + 2]);
                    c0[4 * j + 3] = fmaf(pv0, qw.w, c0[4 * j + 3]);
                    c1[4 * j + 0] = fmaf(pv1, qw.x, c1[4 * j + 0]);
                    c1[4 * j + 1] = fmaf(pv1, qw.y, c1[4 * j + 1]);
                    c1[4 * j + 2] = fmaf(pv1, qw.z, c1[4 * j + 2]);
                    c1[4 * j + 3] = fmaf(pv1, qw.w, c1[4 * j + 3]);
                }
            }
#pragma unroll
            for (int j = 0; j < 16; j++) {
                int c = q * 16 + j;
                float s = g_sc3[g * 128 + c], bb = g_bi3[g * 128 + c];
                float2 res = *(const float2*)(resp + (size_t)c * HW);
                float v0 = fmaxf(fmaf(c0[j], s, bb) + res.x, 0.f);
                float v1 = fmaxf(fmaf(c1[j], s, bb) + res.y, 0.f);
                *(float2*)(op + (size_t)c * HW) = make_float2(v0, v1);
            }
        }
    } else {
        // zero mask: out = relu(bias3 + residual)
#pragma unroll 4
        for (int c = 0; c < 128; c++) {
            float bb = g_bi3[g * 128 + c];
            float2 res = *(const float2*)(resp + (size_t)c * HW);
            float v0 = fmaxf(bb + res.x, 0.f);
            float v1 = fmaxf(bb + res.y, 0.f);
            *(float2*)(op + (size_t)c * HW) = make_float2(v0, v1);
        }
    }
}

// ---------------------------------------------------------------------------
extern "C" void kernel_launch(void* const* d_in, const int* in_sizes, int n_in,
                              void* d_out, int out_size) {
    const float* x    = (const float*)d_in[0];
    const float* mask = (const float*)d_in[1];
    const float* w1   = (const float*)d_in[2];
    const float* g1 = (const float*)d_in[3];
    const float* b1 = (const float*)d_in[4];
    const float* m1 = (const float*)d_in[5];
    const float* v1 = (const float*)d_in[6];
    const float* w2   = (const float*)d_in[7];
    const float* g2 = (const float*)d_in[8];
    const float* b2 = (const float*)d_in[9];
    const float* m2 = (const float*)d_in[10];
    const float* v2 = (const float*)d_in[11];
    const float* w3   = (const float*)d_in[12];
    const float* g3 = (const float*)d_in[13];
    const float* b3 = (const float*)d_in[14];
    const float* m3 = (const float*)d_in[15];
    const float* v3 = (const float*)d_in[16];
    float* out = (float*)d_out;

    bn_prep<<<1, 512>>>(g1, b1, m1, v1, g2, b2, m2, v2, g3, b3, m3, v3);

    k1<<<16 * 4 * 7 * 2, 224>>>(x, mask, w1);

    const int k23_smem = (9216 + 4096) * (int)sizeof(float);  // 53248 B
    cudaFuncSetAttribute(k23, cudaFuncAttributeMaxDynamicSharedMemorySize, k23_smem);
    k23<<<16 * 4 * 7, 224, k23_smem>>>(x, mask, w2, w3, out);
}

// round 5
// speedup vs baseline: 2.2350x; 2.2350x over previous
#include <cuda_runtime.h>
#include <cstdint>

#define HW 3136
#define EPS 1e-5f

// Scratch (device globals: no runtime allocation allowed)
__device__ float g_mid1[16 * 128 * HW];
__device__ float g_mid2[16 * 128 * HW];

// Common decode: 224 threads = 7 warps; warp = patch column, lane: r=l>>2 row,
// cp=l&3 col-pair; thread owns 2 adjacent pixels. Mask is warp-uniform.

// ---------------------------------------------------------------------------
// K1: 1x1 conv (128 -> 8 oc per block) + BN1 + ReLU + mask premult
// grid = (b, g, pr, qc in 0..3)
// ---------------------------------------------------------------------------
__global__ __launch_bounds__(224, 5) void k1(const float* __restrict__ x,
                                             const float* __restrict__ mask,
                                             const float* __restrict__ w1,
                                             const float* __restrict__ bg1,
                                             const float* __restrict__ bb1,
                                             const float* __restrict__ bm1,
                                             const float* __restrict__ bv1) {
    __shared__ __align__(16) float ws[1024];  // [ic][8]

    const int t = threadIdx.x, blk = blockIdx.x;
    const int qc = blk & 3;
    const int rest = blk >> 2;
    const int pr = rest % 7;
    const int bg = rest / 7;
    const int g = bg & 3, b = bg >> 2;

    for (int e = t; e < 1024; e += 224) {
        int j = e >> 7, ic = e & 127;
        ws[ic * 8 + j] = w1[(g * 32 + qc * 8 + j) * 128 + ic];
    }
    __syncthreads();

    const int w = t >> 5, l = t & 31;
    const int r = l >> 2, cp = l & 3;
    const int grow = pr * 8 + r;
    const int col = w * 8 + cp * 2;
    const float m = mask[((b * 4 + g) * 7 + pr) * 7 + w];

    float* op = g_mid1 + (size_t)(b * 128 + g * 32 + qc * 8) * HW + grow * 56 + col;

    if (m != 0.f) {
        const float* xp = x + (size_t)(b * 512 + g * 128) * HW + grow * 56 + col;
        float a0[8], a1[8];
#pragma unroll
        for (int j = 0; j < 8; j++) { a0[j] = 0.f; a1[j] = 0.f; }

        for (int ic0 = 0; ic0 < 128; ic0 += 8) {
            float2 xv[8];
#pragma unroll
            for (int u = 0; u < 8; u++)
                xv[u] = *(const float2*)(xp + (size_t)(ic0 + u) * HW);
#pragma unroll
            for (int u = 0; u < 8; u++) {
                const float4* wp = (const float4*)(ws + (ic0 + u) * 8);
#pragma unroll
                for (int j = 0; j < 2; j++) {
                    float4 q = wp[j];
                    a0[4 * j + 0] = fmaf(xv[u].x, q.x, a0[4 * j + 0]);
                    a0[4 * j + 1] = fmaf(xv[u].x, q.y, a0[4 * j + 1]);
                    a0[4 * j + 2] = fmaf(xv[u].x, q.z, a0[4 * j + 2]);
                    a0[4 * j + 3] = fmaf(xv[u].x, q.w, a0[4 * j + 3]);
                    a1[4 * j + 0] = fmaf(xv[u].y, q.x, a1[4 * j + 0]);
                    a1[4 * j + 1] = fmaf(xv[u].y, q.y, a1[4 * j + 1]);
                    a1[4 * j + 2] = fmaf(xv[u].y, q.z, a1[4 * j + 2]);
                    a1[4 * j + 3] = fmaf(xv[u].y, q.w, a1[4 * j + 3]);
                }
            }
        }
#pragma unroll
        for (int j = 0; j < 8; j++) {
            int c = g * 32 + qc * 8 + j;
            float s = bg1[c] * rsqrtf(bv1[c] + EPS);
            float bb = bb1[c] - bm1[c] * s;
            float v0 = fmaxf(fmaf(m * a0[j], s, bb), 0.f) * m;
            float v1 = fmaxf(fmaf(m * a1[j], s, bb), 0.f) * m;
            *(float2*)(op + (size_t)j * HW) = make_float2(v0, v1);
        }
    } else {
        float2 z = make_float2(0.f, 0.f);
#pragma unroll
        for (int j = 0; j < 8; j++) *(float2*)(op + (size_t)j * HW) = z;
    }
}

// ---------------------------------------------------------------------------
// K2: 3x3 conv (32 -> 8 oc per block, pad 1) + BN2 + ReLU + mask
// grid = (b, g, pr, qc in 0..3)
// ---------------------------------------------------------------------------
__global__ __launch_bounds__(224, 4) void k2(const float* __restrict__ mask,
                                             const float* __restrict__ w2,
                                             const float* __restrict__ bg2,
                                             const float* __restrict__ bb2,
                                             const float* __restrict__ bm2,
                                             const float* __restrict__ bv2) {
    __shared__ __align__(16) float ws[2304];  // [ic][dy][dx][8]

    const int t = threadIdx.x, blk = blockIdx.x;
    const int qc = blk & 3;
    const int rest = blk >> 2;
    const int pr = rest % 7;
    const int bg = rest / 7;
    const int g = bg & 3, b = bg >> 2;

    for (int e = t; e < 2304; e += 224) {
        int j = e / 288;
        int rem = e - j * 288;
        int ic = rem / 9;
        int k = rem - ic * 9;
        ws[(ic * 9 + k) * 8 + j] = w2[((g * 32 + qc * 8 + j) * 32 + ic) * 9 + k];
    }
    __syncthreads();

    const int w = t >> 5, l = t & 31;
    const int r = l >> 2, cp = l & 3;
    const int grow = pr * 8 + r;
    const int col = w * 8 + cp * 2;
    const float m = mask[((b * 4 + g) * 7 + pr) * 7 + w];

    float* op = g_mid2 + (size_t)(b * 128 + g * 32 + qc * 8) * HW + grow * 56 + col;

    if (m != 0.f) {
        const float* mb = g_mid1 + (size_t)(b * 128 + g * 32) * HW + col;
        float a0[8], a1[8];
#pragma unroll
        for (int j = 0; j < 8; j++) { a0[j] = 0.f; a1[j] = 0.f; }

#pragma unroll 2
        for (int ic = 0; ic < 32; ic++) {
            const float* pic = mb + (size_t)ic * HW;
            float xm[3], x2[3];
            float2 xc[3];
#pragma unroll
            for (int dy = 0; dy < 3; dy++) {
                int yy = grow - 1 + dy;
                bool v = (yy >= 0) && (yy < 56);
                const float* p = pic + yy * 56;
                xm[dy] = (v && col > 0) ? p[-1] : 0.f;
                xc[dy] = v ? *(const float2*)p : make_float2(0.f, 0.f);
                x2[dy] = (v && col < 54) ? p[2] : 0.f;
            }
#pragma unroll
            for (int dy = 0; dy < 3; dy++) {
                const float4* wp = (const float4*)(ws + (ic * 9 + dy * 3) * 8);
                float q0 = xm[dy], q1 = xc[dy].x, q2 = xc[dy].y, q3 = x2[dy];
#pragma unroll
                for (int j = 0; j < 2; j++) {
                    float4 wa = wp[j];
                    float4 wb = wp[2 + j];
                    float4 wc = wp[4 + j];
                    a0[4 * j + 0] = fmaf(q0, wa.x, fmaf(q1, wb.x, fmaf(q2, wc.x, a0[4 * j + 0])));
                    a0[4 * j + 1] = fmaf(q0, wa.y, fmaf(q1, wb.y, fmaf(q2, wc.y, a0[4 * j + 1])));
                    a0[4 * j + 2] = fmaf(q0, wa.z, fmaf(q1, wb.z, fmaf(q2, wc.z, a0[4 * j + 2])));
                    a0[4 * j + 3] = fmaf(q0, wa.w, fmaf(q1, wb.w, fmaf(q2, wc.w, a0[4 * j + 3])));
                    a1[4 * j + 0] = fmaf(q1, wa.x, fmaf(q2, wb.x, fmaf(q3, wc.x, a1[4 * j + 0])));
                    a1[4 * j + 1] = fmaf(q1, wa.y, fmaf(q2, wb.y, fmaf(q3, wc.y, a1[4 * j + 1])));
                    a1[4 * j + 2] = fmaf(q1, wa.z, fmaf(q2, wb.z, fmaf(q3, wc.z, a1[4 * j + 2])));
                    a1[4 * j + 3] = fmaf(q1, wa.w, fmaf(q2, wb.w, fmaf(q3, wc.w, a1[4 * j + 3])));
                }
            }
        }
#pragma unroll
        for (int j = 0; j < 8; j++) {
            int c = g * 32 + qc * 8 + j;
            float s = bg2[c] * rsqrtf(bv2[c] + EPS);
            float bb = bb2[c] - bm2[c] * s;
            float v0 = fmaxf(fmaf(a0[j], s, bb), 0.f) * m;
            float v1 = fmaxf(fmaf(a1[j], s, bb), 0.f) * m;
            *(float2*)(op + (size_t)j * HW) = make_float2(v0, v1);
        }
    } else {
        float2 z = make_float2(0.f, 0.f);
#pragma unroll
        for (int j = 0; j < 8; j++) *(float2*)(op + (size_t)j * HW) = z;
    }
}

// ---------------------------------------------------------------------------
// K3: 1x1 conv (32 -> 8 oc per block) + BN3 + residual + ReLU
// grid = (b, g, pr, qc in 0..15)
// ---------------------------------------------------------------------------
__global__ __launch_bounds__(224, 5) void k3(const float* __restrict__ x,
                                             const float* __restrict__ mask,
                                             const float* __restrict__ w3,
                                             const float* __restrict__ bg3,
                                             const float* __restrict__ bb3,
                                             const float* __restrict__ bm3,
                                             const float* __restrict__ bv3,
                                             float* __restrict__ out) {
    __shared__ __align__(16) float ws[256];  // [ic][8]

    const int t = threadIdx.x, blk = blockIdx.x;
    const int qc = blk & 15;
    const int rest = blk >> 4;
    const int pr = rest % 7;
    const int bg = rest / 7;
    const int g = bg & 3, b = bg >> 2;

    for (int e = t; e < 256; e += 224) {
        int j = e >> 5, ic = e & 31;
        ws[ic * 8 + j] = w3[(g * 128 + qc * 8 + j) * 32 + ic];
    }
    __syncthreads();

    const int w = t >> 5, l = t & 31;
    const int r = l >> 2, cp = l & 3;
    const int grow = pr * 8 + r;
    const int col = w * 8 + cp * 2;
    const float m = mask[((b * 4 + g) * 7 + pr) * 7 + w];

    const float* resp = x + (size_t)(b * 512 + g * 128 + qc * 8) * HW + grow * 56 + col;
    float* op = out + (size_t)(b * 512 + g * 128 + qc * 8) * HW + grow * 56 + col;

    float sc[8], bi[8];
#pragma unroll
    for (int j = 0; j < 8; j++) {
        int c = g * 128 + qc * 8 + j;
        float s = bg3[c] * rsqrtf(bv3[c] + EPS);
        sc[j] = s;
        bi[j] = bb3[c] - bm3[c] * s;
    }

    if (m != 0.f) {
        const float* mp = g_mid2 + (size_t)(b * 128 + g * 32) * HW + grow * 56 + col;
        float a0[8], a1[8];
#pragma unroll
        for (int j = 0; j < 8; j++) { a0[j] = 0.f; a1[j] = 0.f; }

        for (int ic0 = 0; ic0 < 32; ic0 += 8) {
            float2 xv[8];
#pragma unroll
            for (int u = 0; u < 8; u++)
                xv[u] = *(const float2*)(mp + (size_t)(ic0 + u) * HW);
#pragma unroll
            for (int u = 0; u < 8; u++) {
                const float4* wp = (const float4*)(ws + (ic0 + u) * 8);
#pragma unroll
                for (int j = 0; j < 2; j++) {
                    float4 q = wp[j];
                    a0[4 * j + 0] = fmaf(xv[u].x, q.x, a0[4 * j + 0]);
                    a0[4 * j + 1] = fmaf(xv[u].x, q.y, a0[4 * j + 1]);
                    a0[4 * j + 2] = fmaf(xv[u].x, q.z, a0[4 * j + 2]);
                    a0[4 * j + 3] = fmaf(xv[u].x, q.w, a0[4 * j + 3]);
                    a1[4 * j + 0] = fmaf(xv[u].y, q.x, a1[4 * j + 0]);
                    a1[4 * j + 1] = fmaf(xv[u].y, q.y, a1[4 * j + 1]);
                    a1[4 * j + 2] = fmaf(xv[u].y, q.z, a1[4 * j + 2]);
                    a1[4 * j + 3] = fmaf(xv[u].y, q.w, a1[4 * j + 3]);
                }
            }
        }
#pragma unroll
        for (int j = 0; j < 8; j++) {
            float2 res = *(const float2*)(resp + (size_t)j * HW);
            float v0 = fmaxf(fmaf(a0[j], sc[j], bi[j]) + res.x, 0.f);
            float v1 = fmaxf(fmaf(a1[j], sc[j], bi[j]) + res.y, 0.f);
            *(float2*)(op + (size_t)j * HW) = make_float2(v0, v1);
        }
    } else {
#pragma unroll
        for (int j = 0; j < 8; j++) {
            float2 res = *(const float2*)(resp + (size_t)j * HW);
            float v0 = fmaxf(bi[j] + res.x, 0.f);
            float v1 = fmaxf(bi[j] + res.y, 0.f);
            *(float2*)(op + (size_t)j * HW) = make_float2(v0, v1);
        }
    }
}

// ---------------------------------------------------------------------------
extern "C" void kernel_launch(void* const* d_in, const int* in_sizes, int n_in,
                              void* d_out, int out_size) {
    const float* x    = (const float*)d_in[0];
    const float* mask = (const float*)d_in[1];
    const float* w1   = (const float*)d_in[2];
    const float* g1 = (const float*)d_in[3];
    const float* b1 = (const float*)d_in[4];
    const float* m1 = (const float*)d_in[5];
    const float* v1 = (const float*)d_in[6];
    const float* w2   = (const float*)d_in[7];
    const float* g2 = (const float*)d_in[8];
    const float* b2 = (const float*)d_in[9];
    const float* m2 = (const float*)d_in[10];
    const float* v2 = (const float*)d_in[11];
    const float* w3   = (const float*)d_in[12];
    const float* g3 = (const float*)d_in[13];
    const float* b3 = (const float*)d_in[14];
    const float* m3 = (const float*)d_in[15];
    const float* v3 = (const float*)d_in[16];
    float* out = (float*)d_out;

    k1<<<16 * 4 * 7 * 4, 224>>>(x, mask, w1, g1, b1, m1, v1);
    k2<<<16 * 4 * 7 * 4, 224>>>(mask, w2, g2, b2, m2, v2);
    k3<<<16 * 4 * 7 * 16, 224>>>(x, mask, w3, g3, b3, m3, v3, out);
}